// round 5
// baseline (speedup 1.0000x reference)
#include <cuda_runtime.h>
#include <math.h>

#define BB 64
#define LQ 32
#define OO 128
#define LK 256
#define DD 128
#define ALPHA_F 12.0f

// ---------------- scratch (no allocations allowed) ----------------
__device__ float g_qn[BB * LQ * DD];
__device__ float g_kn[OO * LK * DD];
__device__ unsigned char g_qbad[BB];       // batch has any masked q token
__device__ unsigned char g_kmask[OO * LK]; // normalized k mask (1 = masked)
__device__ float g_outscale;               // min(exp(ls),100)/(sqrt(Lq*Lk)+1e-6)

// ---------------- prep: mask dtype detection + flags + scale ----------------
// Masks may arrive as 1-byte bool or as int32 (0/1). Under int32 little-endian
// storage every byte at (i % 4 != 0) within the first N bytes is zero; under
// u8 bool with ~10% density over 2K/32K elements, nonzero off-bytes are
// guaranteed in practice. Reading only the first N bytes is safe under both
// interpretations (int32 buffer is 4N bytes).
__global__ void prep_kernel(const void* qm_raw, const void* km_raw,
                            const float* ls) {
    __shared__ int nz_off_q, nz_al_q, nz_off_k, nz_al_k;
    int tid = threadIdx.x;
    if (tid == 0) { nz_off_q = 0; nz_al_q = 0; nz_off_k = 0; nz_al_k = 0; }
    __syncthreads();

    const unsigned char* qb = (const unsigned char*)qm_raw;
    const unsigned char* kb = (const unsigned char*)km_raw;
    int loq = 0, laq = 0, lok = 0, lak = 0;
    for (int i = tid; i < BB * LQ; i += blockDim.x)
        if (qb[i]) { if (i & 3) loq++; else laq++; }
    for (int i = tid; i < OO * LK; i += blockDim.x)
        if (kb[i]) { if (i & 3) lok++; else lak++; }
    if (loq) atomicAdd(&nz_off_q, loq);
    if (laq) atomicAdd(&nz_al_q, laq);
    if (lok) atomicAdd(&nz_off_k, lok);
    if (lak) atomicAdd(&nz_al_k, lak);
    __syncthreads();

    // nonzero off-bytes => u8; only aligned nonzeros => int32; all-zero => u8
    bool q_u8 = (nz_off_q > 0) || (nz_al_q == 0);
    bool k_u8 = (nz_off_k > 0) || (nz_al_k == 0);
    const int* qi = (const int*)qm_raw;
    const int* ki = (const int*)km_raw;

    for (int b = tid; b < BB; b += blockDim.x) {
        unsigned char bad = 0;
        for (int i = 0; i < LQ; i++) {
            int idx = b * LQ + i;
            bool v = q_u8 ? (qb[idx] != 0) : (qi[idx] != 0);
            bad |= (unsigned char)v;
        }
        g_qbad[b] = bad;
    }
    for (int i = tid; i < OO * LK; i += blockDim.x) {
        bool v = k_u8 ? (kb[i] != 0) : (ki[i] != 0);
        g_kmask[i] = (unsigned char)v;
    }
    if (tid == 0) {
        float e = fminf(expf(ls[0]), 100.0f);
        g_outscale = e / (sqrtf((float)(LQ * LK)) + 1e-6f);
    }
}

// ---------------- L2 normalize all q and k rows ----------------
__global__ void normalize_kernel(const float* __restrict__ q,
                                 const float* __restrict__ k) {
    int r = blockIdx.x;
    const float* src;
    float* dst;
    if (r < BB * LQ) {
        src = q + (size_t)r * DD;
        dst = g_qn + (size_t)r * DD;
    } else {
        int r2 = r - BB * LQ;
        src = k + (size_t)r2 * DD;
        dst = g_kn + (size_t)r2 * DD;
    }
    int t = threadIdx.x;  // 128 threads, D == 128
    float x = src[t];
    float ss = x * x;
#pragma unroll
    for (int off = 16; off; off >>= 1)
        ss += __shfl_xor_sync(0xffffffffu, ss, off);
    __shared__ float wred[4];
    __shared__ float s_rinv;
    if ((t & 31) == 0) wred[t >> 5] = ss;
    __syncthreads();
    if (t == 0) {
        float tot = wred[0] + wred[1] + wred[2] + wred[3];
        s_rinv = 1.0f / fmaxf(sqrtf(tot), 1e-12f);
    }
    __syncthreads();
    dst[t] = x * s_rinv;
}

// ---------------- main score kernel ----------------
// grid (O, B), 128 threads. Warp w owns 8 q rows; each lane owns 4 j columns
// per 128-wide k chunk (8i x 4j register tile). Online logsumexp per i across
// chunks, merged across lanes by shuffle.
__global__ void __launch_bounds__(128, 2)
score_kernel(float* __restrict__ out) {
    const int o = blockIdx.x, b = blockIdx.y;
    const int tid = threadIdx.x;
    if (g_qbad[b]) {  // entire batch row is exactly zero (sum over Lq hits -inf)
        if (tid == 0) out[b * OO + o] = 0.0f;
        return;
    }
    extern __shared__ float sm[];
    float* qs = sm;            // 32 x 128
    float* ks = sm + LQ * DD;  // 128 x 132 (padded, conflict-free LDS.128)
    const int KST = 132;

    {  // q tile load (coalesced float4)
        const float4* src = (const float4*)(g_qn + (size_t)b * LQ * DD);
        float4* dst = (float4*)qs;
        for (int i = tid; i < LQ * DD / 4; i += 128) dst[i] = src[i];
    }
    const int warp = tid >> 5, lane = tid & 31;
    const int i0 = warp * 8;

    float m8[8], s8[8];
#pragma unroll
    for (int a = 0; a < 8; a++) { m8[a] = -INFINITY; s8[a] = 0.0f; }

    for (int chunk = 0; chunk < 2; chunk++) {
        const int jbase = chunk * 128;
        __syncthreads();  // qs visible (iter 0) / ks safe to overwrite (iter 1)
        {
            const float4* src =
                (const float4*)(g_kn + ((size_t)o * LK + jbase) * DD);
            for (int t = tid; t < 128 * 32; t += 128) {
                int r = t >> 5, c = t & 31;
                float4 v = src[t];
                *((float4*)(ks + r * KST + c * 4)) = v;
            }
        }
        __syncthreads();

        float acc[8][4];
#pragma unroll
        for (int a = 0; a < 8; a++)
#pragma unroll
            for (int c = 0; c < 4; c++) acc[a][c] = 0.0f;

        for (int d4 = 0; d4 < 32; d4++) {
            float4 kv[4];
#pragma unroll
            for (int c = 0; c < 4; c++)
                kv[c] = *((const float4*)(ks + (lane + 32 * c) * KST + d4 * 4));
#pragma unroll
            for (int a = 0; a < 8; a++) {
                float4 qv =
                    *((const float4*)(qs + (i0 + a) * DD + d4 * 4));
#pragma unroll
                for (int c = 0; c < 4; c++) {
                    acc[a][c] = fmaf(qv.x, kv[c].x, acc[a][c]);
                    acc[a][c] = fmaf(qv.y, kv[c].y, acc[a][c]);
                    acc[a][c] = fmaf(qv.z, kv[c].z, acc[a][c]);
                    acc[a][c] = fmaf(qv.w, kv[c].w, acc[a][c]);
                }
            }
        }
        // fold this chunk into the online logsumexp stats
#pragma unroll
        for (int c = 0; c < 4; c++) {
            const int j = jbase + lane + 32 * c;
            const bool bad = g_kmask[o * LK + j] != 0;
#pragma unroll
            for (int a = 0; a < 8; a++) {
                float v = bad ? -INFINITY : ALPHA_F * acc[a][c];
                float mo = m8[a];
                float mn = fmaxf(mo, v);
                if (mn != -INFINITY) {
                    float e1 = __expf(mo - mn);  // mo=-inf -> 0
                    float e2 = (v == -INFINITY) ? 0.0f : __expf(v - mn);
                    s8[a] = s8[a] * e1 + e2;
                    m8[a] = mn;
                }
            }
        }
    }

    // merge per-row (m,s) across the 32 lanes of the warp
    float rowsum = 0.0f;
#pragma unroll
    for (int a = 0; a < 8; a++) {
        float m = m8[a], s = s8[a];
#pragma unroll
        for (int off = 16; off; off >>= 1) {
            float mo = __shfl_xor_sync(0xffffffffu, m, off);
            float so = __shfl_xor_sync(0xffffffffu, s, off);
            float mn = fmaxf(m, mo);
            if (mn == -INFINITY) {
                m = -INFINITY; s = 0.0f;
            } else {
                s = s * __expf(m - mn) + so * __expf(mo - mn);
                m = mn;
            }
        }
        float lse = (m == -INFINITY) ? -INFINITY : (m + __logf(s));
        rowsum += lse;  // -inf propagates (all-masked k row => whole (b,o) -> 0)
    }
    __shared__ float wsum[4];
    if (lane == 0) wsum[warp] = rowsum;
    __syncthreads();
    if (tid == 0) {
        float tot = wsum[0] + wsum[1] + wsum[2] + wsum[3];
        float res = isfinite(tot) ? (tot / ALPHA_F) * g_outscale : 0.0f;
        out[b * OO + o] = res;
    }
}

// ---------------- launch ----------------
extern "C" void kernel_launch(void* const* d_in, const int* in_sizes, int n_in,
                              void* d_out, int out_size) {
    const float* q = (const float*)d_in[0];
    const float* k = (const float*)d_in[1];
    const void* qm = d_in[2];
    const void* km = d_in[3];
    const float* ls = (const float*)d_in[4];
    float* out = (float*)d_out;

    prep_kernel<<<1, 256>>>(qm, km, ls);
    normalize_kernel<<<BB * LQ + OO * LK, 128>>>(q, k);

    size_t smem = (size_t)(LQ * DD + 128 * 132) * sizeof(float);  // 83968 B
    cudaFuncSetAttribute(score_kernel,
                         cudaFuncAttributeMaxDynamicSharedMemorySize,
                         (int)smem);
    dim3 grid(OO, BB);
    score_kernel<<<grid, 128, smem>>>(out);
}

// round 6
// speedup vs baseline: 1.3423x; 1.3423x over previous
#include <cuda_runtime.h>
#include <math.h>

#define BB 64
#define LQ 32
#define OO 128
#define LK 256
#define DD 128
#define ALPHA_F 12.0f

// ---------------- scratch (no allocations allowed) ----------------
__device__ float g_qn[BB * LQ * DD];
__device__ float g_kn[OO * LK * DD];
__device__ unsigned char g_qbad[BB];  // batch has any masked q token
__device__ float g_outscale;          // min(exp(ls),100)/(sqrt(Lq*Lk)+1e-6)
// dtype-detection flags: [0]=q off-byte nz, [1]=q aligned nz,
//                        [2]=k off-byte nz, [3]=k aligned nz
__device__ int g_flags[4];
__device__ int g_k_u8;  // 1 => k mask is u8 bool, 0 => int32

// ---------------- stage A: zero flags + output scale ----------------
__global__ void initA_kernel(const float* __restrict__ ls) {
    int t = threadIdx.x;
    if (t < 4) g_flags[t] = 0;
    if (t == 0) {
        float e = fminf(expf(ls[0]), 100.0f);
        g_outscale = e / (sqrtf((float)(LQ * LK)) + 1e-6f);
    }
}

// ---------------- stage B: parallel dtype scan (uint4 granular) ----------
// Masks may arrive as 1-byte bool or int32 (0/1). Under little-endian int32
// storage, bytes at i%4!=0 within the first N bytes are all zero; under u8
// bool with ~10% ones, off-bytes are nonzero in practice. Reading the first
// N bytes is safe under both interpretations.
__global__ void detectB_kernel(const void* __restrict__ qm_raw,
                               const void* __restrict__ km_raw) {
    const int NQ = (BB * LQ) / 16;   // 128 uint4
    const int NK = (OO * LK) / 16;   // 2048 uint4
    int gid = blockIdx.x * blockDim.x + threadIdx.x;
    int stride = gridDim.x * blockDim.x;

    unsigned off_q = 0, al_q = 0, off_k = 0, al_k = 0;
    const uint4* qv = (const uint4*)qm_raw;
    const uint4* kv = (const uint4*)km_raw;
    for (int i = gid; i < NQ; i += stride) {
        uint4 v = qv[i];
        off_q |= (v.x & 0xFFFFFF00u) | (v.y & 0xFFFFFF00u) |
                 (v.z & 0xFFFFFF00u) | (v.w & 0xFFFFFF00u);
        al_q |= (v.x & 0xFFu) | (v.y & 0xFFu) | (v.z & 0xFFu) | (v.w & 0xFFu);
    }
    for (int i = gid; i < NK; i += stride) {
        uint4 v = kv[i];
        off_k |= (v.x & 0xFFFFFF00u) | (v.y & 0xFFFFFF00u) |
                 (v.z & 0xFFFFFF00u) | (v.w & 0xFFFFFF00u);
        al_k |= (v.x & 0xFFu) | (v.y & 0xFFu) | (v.z & 0xFFu) | (v.w & 0xFFu);
    }
    // warp-reduce then one atomic per warp per nonzero flag
    for (int off = 16; off; off >>= 1) {
        off_q |= __shfl_xor_sync(0xffffffffu, off_q, off);
        al_q |= __shfl_xor_sync(0xffffffffu, al_q, off);
        off_k |= __shfl_xor_sync(0xffffffffu, off_k, off);
        al_k |= __shfl_xor_sync(0xffffffffu, al_k, off);
    }
    if ((threadIdx.x & 31) == 0) {
        if (off_q) atomicOr(&g_flags[0], 1);
        if (al_q) atomicOr(&g_flags[1], 1);
        if (off_k) atomicOr(&g_flags[2], 1);
        if (al_k) atomicOr(&g_flags[3], 1);
    }
}

// ---------------- stage C: resolve dtype, build per-batch qbad -----------
__global__ void resolveC_kernel(const void* __restrict__ qm_raw) {
    // nonzero off-bytes => u8; only aligned nonzeros => int32; all-zero => u8
    bool q_u8 = (g_flags[0] != 0) || (g_flags[1] == 0);
    bool k_u8 = (g_flags[2] != 0) || (g_flags[3] == 0);
    int t = threadIdx.x;
    if (t == 0) g_k_u8 = k_u8 ? 1 : 0;
    if (t < BB) {
        unsigned acc = 0;
        if (q_u8) {
            const uint4* p = (const uint4*)qm_raw;  // 32 bytes = 2 uint4 / batch
            uint4 a = p[t * 2], b2 = p[t * 2 + 1];
            acc = a.x | a.y | a.z | a.w | b2.x | b2.y | b2.z | b2.w;
        } else {
            const int* p = (const int*)qm_raw;
#pragma unroll
            for (int i = 0; i < LQ; i++) acc |= (unsigned)p[t * LQ + i];
        }
        g_qbad[t] = acc ? 1 : 0;
    }
}

// ---------------- L2 normalize all q and k rows ----------------
__global__ void normalize_kernel(const float* __restrict__ q,
                                 const float* __restrict__ k) {
    int r = blockIdx.x;
    const float* src;
    float* dst;
    if (r < BB * LQ) {
        src = q + (size_t)r * DD;
        dst = g_qn + (size_t)r * DD;
    } else {
        int r2 = r - BB * LQ;
        src = k + (size_t)r2 * DD;
        dst = g_kn + (size_t)r2 * DD;
    }
    int t = threadIdx.x;  // 128 threads, D == 128
    float x = src[t];
    float ss = x * x;
#pragma unroll
    for (int off = 16; off; off >>= 1)
        ss += __shfl_xor_sync(0xffffffffu, ss, off);
    __shared__ float wred[4];
    __shared__ float s_rinv;
    if ((t & 31) == 0) wred[t >> 5] = ss;
    __syncthreads();
    if (t == 0) {
        float tot = wred[0] + wred[1] + wred[2] + wred[3];
        s_rinv = 1.0f / fmaxf(sqrtf(tot), 1e-12f);
    }
    __syncthreads();
    dst[t] = x * s_rinv;
}

// ---------------- main score kernel ----------------
// grid (O, B), 128 threads. Warp w owns 8 q rows; each lane owns 4 j columns
// per 128-wide k chunk (8i x 4j register tile). Online logsumexp per i across
// chunks, merged across lanes by shuffle. Mask read raw with uniform dtype
// branch (no materialized kmask).
__global__ void __launch_bounds__(128, 2)
score_kernel(const void* __restrict__ km_raw, float* __restrict__ out) {
    const int o = blockIdx.x, b = blockIdx.y;
    const int tid = threadIdx.x;
    if (g_qbad[b]) {  // whole batch row is exactly zero (sum over Lq = -inf)
        if (tid == 0) out[b * OO + o] = 0.0f;
        return;
    }
    extern __shared__ float sm[];
    float* qs = sm;            // 32 x 128
    float* ks = sm + LQ * DD;  // 128 x 132 (padded, conflict-free LDS.128)
    const int KST = 132;

    {  // q tile load (coalesced float4)
        const float4* src = (const float4*)(g_qn + (size_t)b * LQ * DD);
        float4* dst = (float4*)qs;
        for (int i = tid; i < LQ * DD / 4; i += 128) dst[i] = src[i];
    }
    const int warp = tid >> 5, lane = tid & 31;
    const int i0 = warp * 8;
    const bool k_u8 = (g_k_u8 != 0);

    float m8[8], s8[8];
#pragma unroll
    for (int a = 0; a < 8; a++) { m8[a] = -INFINITY; s8[a] = 0.0f; }

    for (int chunk = 0; chunk < 2; chunk++) {
        const int jbase = chunk * 128;
        __syncthreads();  // qs visible (iter 0) / ks safe to overwrite (iter 1)
        {
            const float4* src =
                (const float4*)(g_kn + ((size_t)o * LK + jbase) * DD);
            for (int t = tid; t < 128 * 32; t += 128) {
                int r = t >> 5, c = t & 31;
                float4 v = src[t];
                *((float4*)(ks + r * KST + c * 4)) = v;
            }
        }
        __syncthreads();

        // fetch this lane's 4 mask bits up front (overlaps with FMA loop)
        bool badj[4];
#pragma unroll
        for (int c = 0; c < 4; c++) {
            const int j = jbase + lane + 32 * c;
            badj[c] = k_u8
                          ? (((const unsigned char*)km_raw)[o * LK + j] != 0)
                          : (((const int*)km_raw)[o * LK + j] != 0);
        }

        float acc[8][4];
#pragma unroll
        for (int a = 0; a < 8; a++)
#pragma unroll
            for (int c = 0; c < 4; c++) acc[a][c] = 0.0f;

        for (int d4 = 0; d4 < 32; d4++) {
            float4 kv[4];
#pragma unroll
            for (int c = 0; c < 4; c++)
                kv[c] = *((const float4*)(ks + (lane + 32 * c) * KST + d4 * 4));
#pragma unroll
            for (int a = 0; a < 8; a++) {
                float4 qv = *((const float4*)(qs + (i0 + a) * DD + d4 * 4));
#pragma unroll
                for (int c = 0; c < 4; c++) {
                    acc[a][c] = fmaf(qv.x, kv[c].x, acc[a][c]);
                    acc[a][c] = fmaf(qv.y, kv[c].y, acc[a][c]);
                    acc[a][c] = fmaf(qv.z, kv[c].z, acc[a][c]);
                    acc[a][c] = fmaf(qv.w, kv[c].w, acc[a][c]);
                }
            }
        }
        // fold this chunk into the online logsumexp stats
#pragma unroll
        for (int c = 0; c < 4; c++) {
#pragma unroll
            for (int a = 0; a < 8; a++) {
                float v = badj[c] ? -INFINITY : ALPHA_F * acc[a][c];
                float mo = m8[a];
                float mn = fmaxf(mo, v);
                if (mn != -INFINITY) {
                    float e1 = __expf(mo - mn);  // mo=-inf -> 0
                    float e2 = (v == -INFINITY) ? 0.0f : __expf(v - mn);
                    s8[a] = s8[a] * e1 + e2;
                    m8[a] = mn;
                }
            }
        }
    }

    // merge per-row (m,s) across the 32 lanes of the warp
    float rowsum = 0.0f;
#pragma unroll
    for (int a = 0; a < 8; a++) {
        float m = m8[a], s = s8[a];
#pragma unroll
        for (int off = 16; off; off >>= 1) {
            float mo = __shfl_xor_sync(0xffffffffu, m, off);
            float so = __shfl_xor_sync(0xffffffffu, s, off);
            float mn = fmaxf(m, mo);
            if (mn == -INFINITY) {
                m = -INFINITY;
                s = 0.0f;
            } else {
                s = s * __expf(m - mn) + so * __expf(mo - mn);
                m = mn;
            }
        }
        float lse = (m == -INFINITY) ? -INFINITY : (m + __logf(s));
        rowsum += lse;  // -inf propagates (all-masked k row => (b,o) -> 0)
    }
    __shared__ float wsum[4];
    if (lane == 0) wsum[warp] = rowsum;
    __syncthreads();
    if (tid == 0) {
        float tot = wsum[0] + wsum[1] + wsum[2] + wsum[3];
        float res = isfinite(tot) ? (tot / ALPHA_F) * g_outscale : 0.0f;
        out[b * OO + o] = res;
    }
}

// ---------------- launch ----------------
extern "C" void kernel_launch(void* const* d_in, const int* in_sizes, int n_in,
                              void* d_out, int out_size) {
    const float* q = (const float*)d_in[0];
    const float* k = (const float*)d_in[1];
    const void* qm = d_in[2];
    const void* km = d_in[3];
    const float* ls = (const float*)d_in[4];
    float* out = (float*)d_out;

    // normalize first (independent of mask prep; same stream anyway)
    normalize_kernel<<<BB * LQ + OO * LK, 128>>>(q, k);
    initA_kernel<<<1, 32>>>(ls);
    detectB_kernel<<<32, 128>>>(qm, km);
    resolveC_kernel<<<1, 64>>>(qm);

    size_t smem = (size_t)(LQ * DD + 128 * 132) * sizeof(float);  // 83968 B
    cudaFuncSetAttribute(score_kernel,
                         cudaFuncAttributeMaxDynamicSharedMemorySize,
                         (int)smem);
    dim3 grid(OO, BB);
    score_kernel<<<grid, 128, smem>>>(km, out);
}